// round 1
// baseline (speedup 1.0000x reference)
#include <cuda_runtime.h>
#include <math.h>

// Problem constants
constexpr int B_  = 4;
constexpr int S_  = 2048;
constexpr int D_  = 1024;
constexpr int H_  = 16;
constexpr int HD_ = 64;
constexpr int M_  = B_ * S_;   // 8192

// Scratch (static device arrays — allocation-free per harness rules)
__device__ float g_Q[(size_t)M_ * D_];
__device__ float g_K[(size_t)M_ * D_];
__device__ float g_V[(size_t)M_ * D_];
__device__ float g_A[(size_t)M_ * D_];

// ---------------------------------------------------------------------------
// SGEMM: C[M,1024] = A[M,1024] @ W[1024,1024] (+ bias)
// 128x128 block tile, BK=16, 256 threads, 8x8 microtile, float4 everywhere.
// ---------------------------------------------------------------------------
__global__ __launch_bounds__(256, 2)
void sgemm128(const float* __restrict__ A, const float* __restrict__ W,
              const float* __restrict__ bias, float* __restrict__ C) {
    constexpr int Kd = 1024, Nd = 1024;
    __shared__ float As[16][128];   // transposed A tile: As[k][m]
    __shared__ float Bs[16][128];   // Bs[k][n]

    const int tid = threadIdx.x;
    const int tx = tid & 15, ty = tid >> 4;
    const int row0 = blockIdx.y * 128;
    const int col0 = blockIdx.x * 128;

    float acc[8][8];
#pragma unroll
    for (int i = 0; i < 8; i++)
#pragma unroll
        for (int j = 0; j < 8; j++) acc[i][j] = 0.f;

    const int arow = tid >> 2;          // 0..63
    const int acol = (tid & 3) << 2;    // 0,4,8,12
    const int brow = tid >> 5;          // 0..7
    const int bcol = (tid & 31) << 2;   // 0..124

    for (int k0 = 0; k0 < Kd; k0 += 16) {
#pragma unroll
        for (int u = 0; u < 2; u++) {
            int r = arow + u * 64;
            float4 v = *reinterpret_cast<const float4*>(
                A + (size_t)(row0 + r) * Kd + k0 + acol);
            As[acol + 0][r] = v.x;
            As[acol + 1][r] = v.y;
            As[acol + 2][r] = v.z;
            As[acol + 3][r] = v.w;
        }
#pragma unroll
        for (int u = 0; u < 2; u++) {
            int r = brow + u * 8;
            *reinterpret_cast<float4*>(&Bs[r][bcol]) =
                *reinterpret_cast<const float4*>(
                    W + (size_t)(k0 + r) * Nd + col0 + bcol);
        }
        __syncthreads();

#pragma unroll
        for (int kk = 0; kk < 16; kk++) {
            float a[8], b[8];
            *reinterpret_cast<float4*>(a)     = *reinterpret_cast<float4*>(&As[kk][ty * 8]);
            *reinterpret_cast<float4*>(a + 4) = *reinterpret_cast<float4*>(&As[kk][ty * 8 + 4]);
            *reinterpret_cast<float4*>(b)     = *reinterpret_cast<float4*>(&Bs[kk][tx * 8]);
            *reinterpret_cast<float4*>(b + 4) = *reinterpret_cast<float4*>(&Bs[kk][tx * 8 + 4]);
#pragma unroll
            for (int i = 0; i < 8; i++)
#pragma unroll
                for (int j = 0; j < 8; j++)
                    acc[i][j] = fmaf(a[i], b[j], acc[i][j]);
        }
        __syncthreads();
    }

#pragma unroll
    for (int i = 0; i < 8; i++) {
        int r = row0 + ty * 8 + i;
#pragma unroll
        for (int j = 0; j < 8; j += 4) {
            int c = col0 + tx * 8 + j;
            float4 v;
            v.x = acc[i][j];     v.y = acc[i][j + 1];
            v.z = acc[i][j + 2]; v.w = acc[i][j + 3];
            if (bias) {
                v.x += bias[c];     v.y += bias[c + 1];
                v.z += bias[c + 2]; v.w += bias[c + 3];
            }
            *reinterpret_cast<float4*>(C + (size_t)r * Nd + c) = v;
        }
    }
}

// ---------------------------------------------------------------------------
// Flash attention, fp32. One block = 64 query rows of one (b,h).
// Key tile = 32. Online softmax. smem pitches chosen conflict-free:
//   Q/K/V pitch 65 (odd -> per-row bank rotation), P pitch 33.
// ---------------------------------------------------------------------------
__global__ __launch_bounds__(256, 2)
void flash_attn(const float* __restrict__ Qg, const float* __restrict__ Kg,
                const float* __restrict__ Vg, float* __restrict__ Og) {
    constexpr int PIT = 65;
    constexpr int SP  = 33;
    __shared__ float Qs[64 * PIT];
    __shared__ float Ks[32 * PIT];
    __shared__ float Vs[32 * PIT];
    __shared__ float Ps[64 * SP];
    __shared__ float mrow[64], lrow[64], crow[64];

    const int tid = threadIdx.x;
    const int tx = tid & 15, ty = tid >> 4;
    const int b = blockIdx.y >> 4;   // H_ = 16
    const int h = blockIdx.y & 15;
    const int q0 = blockIdx.x * 64;
    const size_t hbase = (size_t)b * S_ * D_ + (size_t)h * HD_;

    // Load Q tile 64x64
#pragma unroll
    for (int u = 0; u < 4; u++) {
        int idx = tid + u * 256;
        int r = idx >> 4;
        int c = (idx & 15) << 2;
        float4 v = *reinterpret_cast<const float4*>(
            Qg + hbase + (size_t)(q0 + r) * D_ + c);
        Qs[r * PIT + c + 0] = v.x;
        Qs[r * PIT + c + 1] = v.y;
        Qs[r * PIT + c + 2] = v.z;
        Qs[r * PIT + c + 3] = v.w;
    }
    if (tid < 64) { mrow[tid] = -INFINITY; lrow[tid] = 0.f; }

    float o[4][4];
#pragma unroll
    for (int i = 0; i < 4; i++)
#pragma unroll
        for (int j = 0; j < 4; j++) o[i][j] = 0.f;

    const int r4 = ty * 4;   // query-row group
    const int c2 = tx * 2;   // score-col group
    const int c4 = tx * 4;   // headdim-col group
    const float scale = 0.03125f;  // 1/sqrt(1024)

    for (int k0 = 0; k0 < S_; k0 += 32) {
        __syncthreads();
        // Load K,V tiles 32x64
#pragma unroll
        for (int u = 0; u < 2; u++) {
            int idx = tid + u * 256;
            int r = idx >> 4;
            int c = (idx & 15) << 2;
            float4 kv = *reinterpret_cast<const float4*>(
                Kg + hbase + (size_t)(k0 + r) * D_ + c);
            float4 vv = *reinterpret_cast<const float4*>(
                Vg + hbase + (size_t)(k0 + r) * D_ + c);
            Ks[r * PIT + c + 0] = kv.x; Ks[r * PIT + c + 1] = kv.y;
            Ks[r * PIT + c + 2] = kv.z; Ks[r * PIT + c + 3] = kv.w;
            Vs[r * PIT + c + 0] = vv.x; Vs[r * PIT + c + 1] = vv.y;
            Vs[r * PIT + c + 2] = vv.z; Vs[r * PIT + c + 3] = vv.w;
        }
        __syncthreads();

        // S = Q K^T (4x2 per thread)
        float s[4][2] = {};
#pragma unroll
        for (int d = 0; d < 64; d++) {
            float b0 = Ks[(c2 + 0) * PIT + d];
            float b1 = Ks[(c2 + 1) * PIT + d];
#pragma unroll
            for (int i = 0; i < 4; i++) {
                float a = Qs[(r4 + i) * PIT + d];
                s[i][0] = fmaf(a, b0, s[i][0]);
                s[i][1] = fmaf(a, b1, s[i][1]);
            }
        }
#pragma unroll
        for (int i = 0; i < 4; i++) {
            Ps[(r4 + i) * SP + c2 + 0] = s[i][0] * scale;
            Ps[(r4 + i) * SP + c2 + 1] = s[i][1] * scale;
        }
        __syncthreads();

        // Online softmax row update (one thread per query row)
        if (tid < 64) {
            float* srow = &Ps[tid * SP];
            float m_old = mrow[tid];
            float mx = m_old;
#pragma unroll
            for (int j = 0; j < 32; j++) mx = fmaxf(mx, srow[j]);
            float cr = __expf(m_old - mx);
            float sum = 0.f;
#pragma unroll
            for (int j = 0; j < 32; j++) {
                float e = __expf(srow[j] - mx);
                srow[j] = e;
                sum += e;
            }
            mrow[tid] = mx;
            lrow[tid] = lrow[tid] * cr + sum;
            crow[tid] = cr;
        }
        __syncthreads();

        // Rescale O and accumulate P @ V (4x4 per thread)
#pragma unroll
        for (int i = 0; i < 4; i++) {
            float cr = crow[r4 + i];
#pragma unroll
            for (int j = 0; j < 4; j++) o[i][j] *= cr;
        }
#pragma unroll
        for (int k = 0; k < 32; k++) {
            float v0 = Vs[k * PIT + c4 + 0];
            float v1 = Vs[k * PIT + c4 + 1];
            float v2 = Vs[k * PIT + c4 + 2];
            float v3 = Vs[k * PIT + c4 + 3];
#pragma unroll
            for (int i = 0; i < 4; i++) {
                float p = Ps[(r4 + i) * SP + k];
                o[i][0] = fmaf(p, v0, o[i][0]);
                o[i][1] = fmaf(p, v1, o[i][1]);
                o[i][2] = fmaf(p, v2, o[i][2]);
                o[i][3] = fmaf(p, v3, o[i][3]);
            }
        }
    }

    // Final normalize + store (lrow stable since last __syncthreads)
#pragma unroll
    for (int i = 0; i < 4; i++) {
        float inv = 1.0f / lrow[r4 + i];
        float4 v;
        v.x = o[i][0] * inv; v.y = o[i][1] * inv;
        v.z = o[i][2] * inv; v.w = o[i][3] * inv;
        *reinterpret_cast<float4*>(
            Og + hbase + (size_t)(q0 + r4 + i) * D_ + c4) = v;
    }
}

// ---------------------------------------------------------------------------
// Launch: 3 projection GEMMs -> flash attention -> output GEMM (+bias)
// ---------------------------------------------------------------------------
extern "C" void kernel_launch(void* const* d_in, const int* in_sizes, int n_in,
                              void* d_out, int out_size) {
    const float* query = (const float*)d_in[0];
    const float* key   = (const float*)d_in[1];
    const float* value = (const float*)d_in[2];
    const float* Wq    = (const float*)d_in[3];
    const float* Wk    = (const float*)d_in[4];
    const float* Wv    = (const float*)d_in[5];
    const float* Wo    = (const float*)d_in[6];
    const float* bo    = (const float*)d_in[7];
    float* out = (float*)d_out;

    float *q, *k, *v, *a;
    cudaGetSymbolAddress((void**)&q, g_Q);
    cudaGetSymbolAddress((void**)&k, g_K);
    cudaGetSymbolAddress((void**)&v, g_V);
    cudaGetSymbolAddress((void**)&a, g_A);

    dim3 gg(D_ / 128, M_ / 128);   // (8, 64)
    sgemm128<<<gg, 256>>>(query, Wq, nullptr, q);
    sgemm128<<<gg, 256>>>(key,   Wk, nullptr, k);
    sgemm128<<<gg, 256>>>(value, Wv, nullptr, v);
    flash_attn<<<dim3(S_ / 64, B_ * H_), 256>>>(q, k, v, a);
    sgemm128<<<gg, 256>>>(a, Wo, bo, out);
}